// round 5
// baseline (speedup 1.0000x reference)
#include <cuda_runtime.h>
#include <math.h>

#define B_N     16
#define C_CH    256
#define L_LEN   8192
#define DEPTH_N 12

#define NTH     256
#define NSLOT   16               // pairs per thread
#define BUFB    34816u           // bytes per smem buffer (8704 floats)

using u64 = unsigned long long;
using u32 = unsigned int;

// padded relative word offset for element index e (may be < 0): e + 2*floor(e/32)
__host__ __device__ constexpr int padrel(int e) {
    int q = (e >= 0) ? (e / 32) : -(((31 - e) / 32));
    return e + 2 * q;
}

__device__ __forceinline__ u64 pk2(float lo, float hi) {
    u64 r; asm("mov.b64 %0,{%1,%2};" : "=l"(r) : "f"(lo), "f"(hi)); return r;
}
__device__ __forceinline__ void upk2(u64 v, float& lo, float& hi) {
    asm("mov.b64 {%0,%1},%2;" : "=f"(lo), "=f"(hi) : "l"(v));
}
__device__ __forceinline__ u64 fma2(u64 a, u64 b, u64 c) {
    u64 r; asm("fma.rn.f32x2 %0,%1,%2,%3;" : "=l"(r) : "l"(a), "l"(b), "l"(c)); return r;
}
__device__ __forceinline__ u64 mul2(u64 a, u64 b) {
    u64 r; asm("mul.rn.f32x2 %0,%1,%2;" : "=l"(r) : "l"(a), "l"(b)); return r;
}
// 32-bit shared-memory access (1 reg per address, ptxas folds const offsets)
__device__ __forceinline__ u64 lds64(u32 a) {
    u64 r; asm volatile("ld.shared.b64 %0,[%1];" : "=l"(r) : "r"(a)); return r;
}
__device__ __forceinline__ void sts64(u32 a, u64 v) {
    asm volatile("st.shared.b64 [%0],%1;" :: "r"(a), "l"(v));
}

// ---------- Phase A: block layout (thread owns pairs 16t..16t+15) ----------
template<int DD, int SF>
__device__ __forceinline__ void levelA(
    u64 (&rl)[NSLOT], u64 (&y2)[NSLOT], u32 ob, u32 nb,
    bool ge1, bool ge2,
    u64 a0, u64 a1, u64 a2, u64 a3,
    u64 b0, u64 b1, u64 b2, u64 b3)
{
    __syncthreads();
#pragma unroll
    for (int p = NSLOT - 1; p >= 0; --p) {
        u64 t0 = rl[p];
        u64 t1, t2, t3;
        if (p >= 1 * DD) t1 = rl[p - 1 * DD];
        else { bool ok = ((1 * DD - p + 15) / 16 <= 1) ? ge1 : ge2;
               t1 = ok ? lds64(ob + (u32)(4 * padrel(2 * (p - 1 * DD)))) : 0; }
        if (p >= 2 * DD) t2 = rl[p - 2 * DD];
        else { bool ok = ((2 * DD - p + 15) / 16 <= 1) ? ge1 : ge2;
               t2 = ok ? lds64(ob + (u32)(4 * padrel(2 * (p - 2 * DD)))) : 0; }
        if (p >= 3 * DD) t3 = rl[p - 3 * DD];
        else { bool ok = ((3 * DD - p + 15) / 16 <= 1) ? ge1 : ge2;
               t3 = ok ? lds64(ob + (u32)(4 * padrel(2 * (p - 3 * DD)))) : 0; }
        y2[p] = fma2(b3, t0, fma2(b2, t1, fma2(b1, t2, fma2(b0, t3, y2[p]))));
        rl[p] = fma2(a3, t0, fma2(a2, t1, fma2(a1, t2, mul2(a0, t3))));
    }
#pragma unroll
    for (int p = SF; p < NSLOT; ++p)
        sts64(nb + 8u * p, rl[p]);
}

// ---------- Phase B: tile16 layout (thread (T,r) owns pairs 256T + r + 16j) ----------
template<int DJ, int SF, bool STORE>
__device__ __forceinline__ void levelB(
    u64 (&rl)[NSLOT], u64 (&y2)[NSLOT], u32 ob, u32 nb,
    bool tge1, bool tge2,
    u64 a0, u64 a1, u64 a2, u64 a3,
    u64 b0, u64 b1, u64 b2, u64 b3)
{
    __syncthreads();
#pragma unroll
    for (int j = NSLOT - 1; j >= 0; --j) {
        u64 t0 = rl[j];
        u64 t1, t2, t3;
        if (j >= 1 * DJ) t1 = rl[j - 1 * DJ];
        else { bool ok = (1 * DJ - j <= 16) ? tge1 : tge2;
               t1 = ok ? lds64(ob + (u32)(136 * (j - 1 * DJ))) : 0; }
        if (j >= 2 * DJ) t2 = rl[j - 2 * DJ];
        else { bool ok = (2 * DJ - j <= 16) ? tge1 : tge2;
               t2 = ok ? lds64(ob + (u32)(136 * (j - 2 * DJ))) : 0; }
        if (j >= 3 * DJ) t3 = rl[j - 3 * DJ];
        else { bool ok = (3 * DJ - j <= 16) ? tge1 : tge2;
               t3 = ok ? lds64(ob + (u32)(136 * (j - 3 * DJ))) : 0; }
        y2[j] = fma2(b3, t0, fma2(b2, t1, fma2(b1, t2, fma2(b0, t3, y2[j]))));
        rl[j] = fma2(a3, t0, fma2(a2, t1, fma2(a1, t2, mul2(a0, t3))));
    }
    if (STORE) {
#pragma unroll
        for (int j = SF; j < NSLOT; ++j)
            sts64(nb + 136u * j, rl[j]);
    }
}

// ---------- Phase C: cyclic-256 layout (pure register, no smem, no sync) ----------
template<int DK>
__device__ __forceinline__ void levelC(
    u64 (&rl)[NSLOT], u64 (&y2)[NSLOT],
    u64 a0, u64 a1, u64 a2, u64 a3,
    u64 b0, u64 b1, u64 b2, u64 b3)
{
#pragma unroll
    for (int k = NSLOT - 1; k >= 0; --k) {
        u64 t0 = rl[k];
        u64 t1 = (k >= 1 * DK) ? rl[k - 1 * DK] : 0;
        u64 t2 = (k >= 2 * DK) ? rl[k - 2 * DK] : 0;
        u64 t3 = (k >= 3 * DK) ? rl[k - 3 * DK] : 0;
        y2[k] = fma2(b3, t0, fma2(b2, t1, fma2(b1, t2, fma2(b0, t3, y2[k]))));
        rl[k] = fma2(a3, t0, fma2(a2, t1, fma2(a1, t2, mul2(a0, t3))));
    }
}

__global__ void __launch_bounds__(NTH, 3)
mr_kernel(const float* __restrict__ x, const float* __restrict__ h0,
          const float* __restrict__ h1, const float* __restrict__ w,
          float* __restrict__ out)
{
    extern __shared__ float sm[];
    const u32 sb = (u32)__cvta_generic_to_shared(sm);
    float* scr = (float*)((char*)sm + 2 * BUFB);     // 8 warps x 3 floats

    const int tid  = threadIdx.x;
    const int lane = tid & 31;
    const int warp = tid >> 5;
    const int T    = tid >> 4;
    const int rr   = tid & 15;
    const int row  = blockIdx.x;                     // b*C + c
    const int c    = row & (C_CH - 1);
    const float* xr = x + (size_t)row * L_LEN;

    const bool ge1  = (tid >= 1), ge2 = (tid >= 2);
    const bool tge1 = (T >= 1),  tge2 = (T >= 2);

    // 32-bit smem addresses
    const u32 blk0 = sb + 136u * tid;
    const u32 blk1 = blk0 + BUFB;
    const u32 til0 = sb + 2176u * T + 8u * rr;
    const u32 til1 = til0 + BUFB;
    const u32 cyc0 = sb + 8u * tid + 8u * (tid >> 4);
    const u32 cyc1 = cyc0 + BUFB;

    // ---- load 8x float4 (x[32] window) ----
    float4 v0, v1, v2, v3, v4, v5, v6, v7;
    {
        const float4* x4 = (const float4*)xr + tid * 8;
        v0 = x4[0]; v1 = x4[1]; v2 = x4[2]; v3 = x4[3];
        v4 = x4[4]; v5 = x4[5]; v6 = x4[6]; v7 = x4[7];
    }
    if (lane == 31) {            // cross-warp x halo for d=1
        scr[3 * warp + 0] = v7.y;   // x[29]
        scr[3 * warp + 1] = v7.z;   // x[30]
        scr[3 * warp + 2] = v7.w;   // x[31]
    }

    // ---- per-channel coefficients ----
    const float c0 = __ldg(h0 + c * 4 + 0), c1 = __ldg(h0 + c * 4 + 1);
    const float c2 = __ldg(h0 + c * 4 + 2), c3 = __ldg(h0 + c * 4 + 3);
    const float e0 = __ldg(h1 + c * 4 + 0), e1 = __ldg(h1 + c * 4 + 1);
    const float e2 = __ldg(h1 + c * 4 + 2), e3 = __ldg(h1 + c * 4 + 3);
    const float* wc = w + c * (DEPTH_N + 2);

    // x halo elements -1,-2,-3 via shuffle (lane 0 via scratch)
    float xm1 = __shfl_up_sync(0xffffffffu, v7.w, 1);
    float xm2 = __shfl_up_sync(0xffffffffu, v7.z, 1);
    float xm3 = __shfl_up_sync(0xffffffffu, v7.y, 1);
    __syncthreads();
    if (lane == 0) {
        if (tid > 0) {
            xm1 = scr[3 * (warp - 1) + 2];
            xm2 = scr[3 * (warp - 1) + 1];
            xm3 = scr[3 * (warp - 1) + 0];
        } else { xm1 = 0.0f; xm2 = 0.0f; xm3 = 0.0f; }
    }

    const u64 a0 = pk2(c0, c0), a1 = pk2(c1, c1), a2 = pk2(c2, c2), a3 = pk2(c3, c3);

    // ---- level d=1 in pair form, streaming off the float4 window + y init ----
    // y = w13*x + w12*conv(x,h1,1) (w13 folded into tap-0 coeff); rl = conv(x,h0,1)
    u64 rl[NSLOT], y2[NSLOT];
    {
        const float w13 = __ldg(wc + 13);
        const float w12 = __ldg(wc + 12);
        const u64 g0 = pk2(w12 * e0, w12 * e0);
        const u64 g1 = pk2(w12 * e1, w12 * e1);
        const u64 g2 = pk2(w12 * e2, w12 * e2);
        const float g3s = w13 + w12 * e3;
        const u64 g3 = pk2(g3s, g3s);

        float pw = xm1, pz = xm2, py = xm3;   // prev float4 .w/.z/.y (x[-1],x[-2],x[-3])
#define L1_STEP(i, V)                                                            \
        {                                                                        \
            u64 t0 = pk2(V.x, V.y);                                              \
            u64 t1 = pk2(pw, V.x);                                               \
            u64 t2 = pk2(pz, pw);                                                \
            u64 t3 = pk2(py, pz);                                                \
            y2[2*(i)]   = fma2(g3, t0, fma2(g2, t1, fma2(g1, t2, mul2(g0, t3))));\
            rl[2*(i)]   = fma2(a3, t0, fma2(a2, t1, fma2(a1, t2, mul2(a0, t3))));\
            u64 s0 = pk2(V.z, V.w);                                              \
            u64 s1 = pk2(V.y, V.z);                                              \
            u64 s2 = t0;                                                         \
            u64 s3 = t1;                                                         \
            y2[2*(i)+1] = fma2(g3, s0, fma2(g2, s1, fma2(g1, s2, mul2(g0, s3))));\
            rl[2*(i)+1] = fma2(a3, s0, fma2(a2, s1, fma2(a1, s2, mul2(a0, s3))));\
            pw = V.w; pz = V.z; py = V.y;                                        \
        }
        L1_STEP(0, v0) L1_STEP(1, v1) L1_STEP(2, v2) L1_STEP(3, v3)
        L1_STEP(4, v4) L1_STEP(5, v5) L1_STEP(6, v6) L1_STEP(7, v7)
#undef L1_STEP
        // store only the slots d=2's remote taps read (slots 13..15)
#pragma unroll
        for (int p = 13; p < NSLOT; ++p)
            sts64(blk0 + 8u * p, rl[p]);
    }

#define COEFFS(WI)                                                              \
        const float wi = __ldg(wc + (WI));                                      \
        const u64 b0 = pk2(wi * e0, wi * e0);                                   \
        const u64 b1 = pk2(wi * e1, wi * e1);                                   \
        const u64 b2 = pk2(wi * e2, wi * e2);                                   \
        const u64 b3 = pk2(wi * e3, wi * e3);

    // ---- Phase A: d=2,4,8,16 ----
    { COEFFS(11) levelA<1, 10>(rl, y2, blk0, blk1, ge1, ge2, a0, a1, a2, a3, b0, b1, b2, b3); }
    { COEFFS(10) levelA<2,  4>(rl, y2, blk1, blk0, ge1, ge2, a0, a1, a2, a3, b0, b1, b2, b3); }
    { COEFFS( 9) levelA<4,  0>(rl, y2, blk0, blk1, ge1, ge2, a0, a1, a2, a3, b0, b1, b2, b3); }
    { COEFFS( 8) levelA<8,  0>(rl, y2, blk1, blk0, ge1, ge2, a0, a1, a2, a3, b0, b1, b2, b3); }

    // ---- T1: block -> tile16 (y2 through smem; rl re-read from d=16's store) ----
    __syncthreads();
#pragma unroll
    for (int j = 0; j < NSLOT; ++j)
        sts64(blk1 + 8u * j, y2[j]);
    __syncthreads();
#pragma unroll
    for (int j = 0; j < NSLOT; ++j) {
        y2[j] = lds64(til1 + 136u * j);
        rl[j] = lds64(til0 + 136u * j);
    }

    // ---- Phase B: d=32,64,128,256 ----
    { COEFFS(7) levelB<1, 10, true >(rl, y2, til0, til1, tge1, tge2, a0, a1, a2, a3, b0, b1, b2, b3); }
    { COEFFS(6) levelB<2,  4, true >(rl, y2, til1, til0, tge1, tge2, a0, a1, a2, a3, b0, b1, b2, b3); }
    { COEFFS(5) levelB<4,  0, true >(rl, y2, til0, til1, tge1, tge2, a0, a1, a2, a3, b0, b1, b2, b3); }
    { COEFFS(4) levelB<8,  0, true >(rl, y2, til1, til0, tge1, tge2, a0, a1, a2, a3, b0, b1, b2, b3); }

    // ---- T2: tile16 -> cyclic-256 ----
    __syncthreads();
#pragma unroll
    for (int j = 0; j < NSLOT; ++j)
        sts64(til1 + 136u * j, y2[j]);
    __syncthreads();
#pragma unroll
    for (int k = 0; k < NSLOT; ++k) {
        y2[k] = lds64(cyc1 + 2176u * k);
        rl[k] = lds64(cyc0 + 2176u * k);
    }

    // ---- Phase C: d=512,1024,2048 — pure register ----
    { COEFFS(3) levelC<1>(rl, y2, a0, a1, a2, a3, b0, b1, b2, b3); }
    { COEFFS(2) levelC<2>(rl, y2, a0, a1, a2, a3, b0, b1, b2, b3); }
    { COEFFS(1) levelC<4>(rl, y2, a0, a1, a2, a3, b0, b1, b2, b3); }
#undef COEFFS

    // ---- final: y += w0*res_lo; exact GELU; coalesced STG.64 (cyclic) ----
    {
        const float w0v = __ldg(wc + 0);
        const u64 w0p = pk2(w0v, w0v);
        float2* o2 = (float2*)(out + (size_t)row * L_LEN);
#pragma unroll
        for (int k = 0; k < NSLOT; ++k) {
            u64 yf = fma2(w0p, rl[k], y2[k]);
            float lo, hi; upk2(yf, lo, hi);
            lo = 0.5f * lo * (1.0f + erff(lo * 0.70710678118654752f));
            hi = 0.5f * hi * (1.0f + erff(hi * 0.70710678118654752f));
            o2[tid + 256 * k] = make_float2(lo, hi);
        }
    }
}

extern "C" void kernel_launch(void* const* d_in, const int* in_sizes, int n_in,
                              void* d_out, int out_size)
{
    (void)in_sizes; (void)n_in; (void)out_size;
    const float* x  = (const float*)d_in[0];
    const float* h0 = (const float*)d_in[1];
    const float* h1 = (const float*)d_in[2];
    const float* w  = (const float*)d_in[3];
    float* out = (float*)d_out;

    const int smem_bytes = 2 * BUFB + 128;   // 69,760 B
    cudaFuncSetAttribute(mr_kernel, cudaFuncAttributeMaxDynamicSharedMemorySize, smem_bytes);
    mr_kernel<<<B_N * C_CH, NTH, smem_bytes>>>(x, h0, h1, w, out);
}

// round 6
// speedup vs baseline: 1.0010x; 1.0010x over previous
#include <cuda_runtime.h>
#include <math.h>

#define B_N     16
#define C_CH    256
#define L_LEN   8192
#define DEPTH_N 12

#define NTH     256
#define NSLOT   16               // pairs per thread
#define BUFB    34816u           // bytes per smem buffer (8704 floats)

using u64 = unsigned long long;
using u32 = unsigned int;

// padded relative word offset for element index e (may be < 0): e + 2*floor(e/32)
__host__ __device__ constexpr int padrel(int e) {
    int q = (e >= 0) ? (e / 32) : -(((31 - e) / 32));
    return e + 2 * q;
}

__device__ __forceinline__ u64 pk2(float lo, float hi) {
    u64 r; asm("mov.b64 %0,{%1,%2};" : "=l"(r) : "f"(lo), "f"(hi)); return r;
}
__device__ __forceinline__ void upk2(u64 v, float& lo, float& hi) {
    asm("mov.b64 {%0,%1},%2;" : "=f"(lo), "=f"(hi) : "l"(v));
}
__device__ __forceinline__ u64 fma2(u64 a, u64 b, u64 c) {
    u64 r; asm("fma.rn.f32x2 %0,%1,%2,%3;" : "=l"(r) : "l"(a), "l"(b), "l"(c)); return r;
}
__device__ __forceinline__ u64 mul2(u64 a, u64 b) {
    u64 r; asm("mul.rn.f32x2 %0,%1,%2;" : "=l"(r) : "l"(a), "l"(b)); return r;
}
// 32-bit shared-memory access (1 reg per address, ptxas folds const offsets)
__device__ __forceinline__ u64 lds64(u32 a) {
    u64 r; asm volatile("ld.shared.b64 %0,[%1];" : "=l"(r) : "r"(a)); return r;
}
__device__ __forceinline__ void sts64(u32 a, u64 v) {
    asm volatile("st.shared.b64 [%0],%1;" :: "r"(a), "l"(v));
}

// ---------- Phase A: block layout (thread owns pairs 16t..16t+15) ----------
template<int DD, int SF>
__device__ __forceinline__ void levelA(
    u64 (&rl)[NSLOT], u64 (&y2)[NSLOT], u32 ob, u32 nb,
    bool ge1, bool ge2,
    u64 a0, u64 a1, u64 a2, u64 a3,
    u64 b0, u64 b1, u64 b2, u64 b3)
{
    __syncthreads();
#pragma unroll
    for (int p = NSLOT - 1; p >= 0; --p) {
        u64 t0 = rl[p];
        u64 t1, t2, t3;
        if (p >= 1 * DD) t1 = rl[p - 1 * DD];
        else { bool ok = ((1 * DD - p + 15) / 16 <= 1) ? ge1 : ge2;
               t1 = ok ? lds64(ob + (u32)(4 * padrel(2 * (p - 1 * DD)))) : 0; }
        if (p >= 2 * DD) t2 = rl[p - 2 * DD];
        else { bool ok = ((2 * DD - p + 15) / 16 <= 1) ? ge1 : ge2;
               t2 = ok ? lds64(ob + (u32)(4 * padrel(2 * (p - 2 * DD)))) : 0; }
        if (p >= 3 * DD) t3 = rl[p - 3 * DD];
        else { bool ok = ((3 * DD - p + 15) / 16 <= 1) ? ge1 : ge2;
               t3 = ok ? lds64(ob + (u32)(4 * padrel(2 * (p - 3 * DD)))) : 0; }
        y2[p] = fma2(b3, t0, fma2(b2, t1, fma2(b1, t2, fma2(b0, t3, y2[p]))));
        rl[p] = fma2(a3, t0, fma2(a2, t1, fma2(a1, t2, mul2(a0, t3))));
    }
#pragma unroll
    for (int p = SF; p < NSLOT; ++p)
        sts64(nb + 8u * p, rl[p]);
}

// ---------- Phase B: tile16 layout (thread (T,r) owns pairs 256T + r + 16j) ----------
template<int DJ, int SF, bool STORE>
__device__ __forceinline__ void levelB(
    u64 (&rl)[NSLOT], u64 (&y2)[NSLOT], u32 ob, u32 nb,
    bool tge1, bool tge2,
    u64 a0, u64 a1, u64 a2, u64 a3,
    u64 b0, u64 b1, u64 b2, u64 b3)
{
    __syncthreads();
#pragma unroll
    for (int j = NSLOT - 1; j >= 0; --j) {
        u64 t0 = rl[j];
        u64 t1, t2, t3;
        if (j >= 1 * DJ) t1 = rl[j - 1 * DJ];
        else { bool ok = (1 * DJ - j <= 16) ? tge1 : tge2;
               t1 = ok ? lds64(ob + (u32)(136 * (j - 1 * DJ))) : 0; }
        if (j >= 2 * DJ) t2 = rl[j - 2 * DJ];
        else { bool ok = (2 * DJ - j <= 16) ? tge1 : tge2;
               t2 = ok ? lds64(ob + (u32)(136 * (j - 2 * DJ))) : 0; }
        if (j >= 3 * DJ) t3 = rl[j - 3 * DJ];
        else { bool ok = (3 * DJ - j <= 16) ? tge1 : tge2;
               t3 = ok ? lds64(ob + (u32)(136 * (j - 3 * DJ))) : 0; }
        y2[j] = fma2(b3, t0, fma2(b2, t1, fma2(b1, t2, fma2(b0, t3, y2[j]))));
        rl[j] = fma2(a3, t0, fma2(a2, t1, fma2(a1, t2, mul2(a0, t3))));
    }
    if (STORE) {
#pragma unroll
        for (int j = SF; j < NSLOT; ++j)
            sts64(nb + 136u * j, rl[j]);
    }
}

// ---------- Phase C: cyclic-256 layout (pure register, no smem, no sync) ----------
template<int DK>
__device__ __forceinline__ void levelC(
    u64 (&rl)[NSLOT], u64 (&y2)[NSLOT],
    u64 a0, u64 a1, u64 a2, u64 a3,
    u64 b0, u64 b1, u64 b2, u64 b3)
{
#pragma unroll
    for (int k = NSLOT - 1; k >= 0; --k) {
        u64 t0 = rl[k];
        u64 t1 = (k >= 1 * DK) ? rl[k - 1 * DK] : 0;
        u64 t2 = (k >= 2 * DK) ? rl[k - 2 * DK] : 0;
        u64 t3 = (k >= 3 * DK) ? rl[k - 3 * DK] : 0;
        y2[k] = fma2(b3, t0, fma2(b2, t1, fma2(b1, t2, fma2(b0, t3, y2[k]))));
        rl[k] = fma2(a3, t0, fma2(a2, t1, fma2(a1, t2, mul2(a0, t3))));
    }
}

__global__ void __launch_bounds__(NTH, 3)
mr_kernel(const float* __restrict__ x, const float* __restrict__ h0,
          const float* __restrict__ h1, const float* __restrict__ w,
          float* __restrict__ out)
{
    extern __shared__ float sm[];
    const u32 sb = (u32)__cvta_generic_to_shared(sm);
    float* scr = (float*)((char*)sm + 2 * BUFB);     // 8 warps x 3 floats

    const int tid  = threadIdx.x;
    const int lane = tid & 31;
    const int warp = tid >> 5;
    const int T    = tid >> 4;
    const int rr   = tid & 15;
    const int row  = blockIdx.x;                     // b*C + c
    const int c    = row & (C_CH - 1);
    const float* xr = x + (size_t)row * L_LEN;

    const bool ge1  = (tid >= 1), ge2 = (tid >= 2);
    const bool tge1 = (T >= 1),  tge2 = (T >= 2);

    // 32-bit smem addresses
    const u32 blk0 = sb + 136u * tid;
    const u32 blk1 = blk0 + BUFB;
    const u32 til0 = sb + 2176u * T + 8u * rr;
    const u32 til1 = til0 + BUFB;
    const u32 cyc0 = sb + 8u * tid + 8u * (tid >> 4);
    const u32 cyc1 = cyc0 + BUFB;

    // ---- load 8x float4 (x[32] window) ----
    float4 v0, v1, v2, v3, v4, v5, v6, v7;
    {
        const float4* x4 = (const float4*)xr + tid * 8;
        v0 = x4[0]; v1 = x4[1]; v2 = x4[2]; v3 = x4[3];
        v4 = x4[4]; v5 = x4[5]; v6 = x4[6]; v7 = x4[7];
    }
    if (lane == 31) {            // cross-warp x halo for d=1
        scr[3 * warp + 0] = v7.y;   // x[29]
        scr[3 * warp + 1] = v7.z;   // x[30]
        scr[3 * warp + 2] = v7.w;   // x[31]
    }

    // ---- per-channel coefficients ----
    const float c0 = __ldg(h0 + c * 4 + 0), c1 = __ldg(h0 + c * 4 + 1);
    const float c2 = __ldg(h0 + c * 4 + 2), c3 = __ldg(h0 + c * 4 + 3);
    const float e0 = __ldg(h1 + c * 4 + 0), e1 = __ldg(h1 + c * 4 + 1);
    const float e2 = __ldg(h1 + c * 4 + 2), e3 = __ldg(h1 + c * 4 + 3);
    const float* wc = w + c * (DEPTH_N + 2);

    // x halo elements -1,-2,-3 via shuffle (lane 0 via scratch)
    float xm1 = __shfl_up_sync(0xffffffffu, v7.w, 1);
    float xm2 = __shfl_up_sync(0xffffffffu, v7.z, 1);
    float xm3 = __shfl_up_sync(0xffffffffu, v7.y, 1);
    __syncthreads();
    if (lane == 0) {
        if (tid > 0) {
            xm1 = scr[3 * (warp - 1) + 2];
            xm2 = scr[3 * (warp - 1) + 1];
            xm3 = scr[3 * (warp - 1) + 0];
        } else { xm1 = 0.0f; xm2 = 0.0f; xm3 = 0.0f; }
    }

    const u64 a0 = pk2(c0, c0), a1 = pk2(c1, c1), a2 = pk2(c2, c2), a3 = pk2(c3, c3);

    // ---- level d=1 in pair form, streaming off the float4 window + y init ----
    // y = w13*x + w12*conv(x,h1,1) (w13 folded into tap-0 coeff); rl = conv(x,h0,1)
    u64 rl[NSLOT], y2[NSLOT];
    {
        const float w13 = __ldg(wc + 13);
        const float w12 = __ldg(wc + 12);
        const u64 g0 = pk2(w12 * e0, w12 * e0);
        const u64 g1 = pk2(w12 * e1, w12 * e1);
        const u64 g2 = pk2(w12 * e2, w12 * e2);
        const float g3s = w13 + w12 * e3;
        const u64 g3 = pk2(g3s, g3s);

        float pw = xm1, pz = xm2, py = xm3;   // prev float4 .w/.z/.y (x[-1],x[-2],x[-3])
#define L1_STEP(i, V)                                                            \
        {                                                                        \
            u64 t0 = pk2(V.x, V.y);                                              \
            u64 t1 = pk2(pw, V.x);                                               \
            u64 t2 = pk2(pz, pw);                                                \
            u64 t3 = pk2(py, pz);                                                \
            y2[2*(i)]   = fma2(g3, t0, fma2(g2, t1, fma2(g1, t2, mul2(g0, t3))));\
            rl[2*(i)]   = fma2(a3, t0, fma2(a2, t1, fma2(a1, t2, mul2(a0, t3))));\
            u64 s0 = pk2(V.z, V.w);                                              \
            u64 s1 = pk2(V.y, V.z);                                              \
            u64 s2 = t0;                                                         \
            u64 s3 = t1;                                                         \
            y2[2*(i)+1] = fma2(g3, s0, fma2(g2, s1, fma2(g1, s2, mul2(g0, s3))));\
            rl[2*(i)+1] = fma2(a3, s0, fma2(a2, s1, fma2(a1, s2, mul2(a0, s3))));\
            pw = V.w; pz = V.z; py = V.y;                                        \
        }
        L1_STEP(0, v0) L1_STEP(1, v1) L1_STEP(2, v2) L1_STEP(3, v3)
        L1_STEP(4, v4) L1_STEP(5, v5) L1_STEP(6, v6) L1_STEP(7, v7)
#undef L1_STEP
        // store only the slots d=2's remote taps read (slots 13..15)
#pragma unroll
        for (int p = 13; p < NSLOT; ++p)
            sts64(blk0 + 8u * p, rl[p]);
    }

#define COEFFS(WI)                                                              \
        const float wi = __ldg(wc + (WI));                                      \
        const u64 b0 = pk2(wi * e0, wi * e0);                                   \
        const u64 b1 = pk2(wi * e1, wi * e1);                                   \
        const u64 b2 = pk2(wi * e2, wi * e2);                                   \
        const u64 b3 = pk2(wi * e3, wi * e3);

    // ---- Phase A: d=2,4,8,16 ----
    { COEFFS(11) levelA<1, 10>(rl, y2, blk0, blk1, ge1, ge2, a0, a1, a2, a3, b0, b1, b2, b3); }
    { COEFFS(10) levelA<2,  4>(rl, y2, blk1, blk0, ge1, ge2, a0, a1, a2, a3, b0, b1, b2, b3); }
    { COEFFS( 9) levelA<4,  0>(rl, y2, blk0, blk1, ge1, ge2, a0, a1, a2, a3, b0, b1, b2, b3); }
    { COEFFS( 8) levelA<8,  0>(rl, y2, blk1, blk0, ge1, ge2, a0, a1, a2, a3, b0, b1, b2, b3); }

    // ---- T1: block -> tile16 (y2 through smem; rl re-read from d=16's store) ----
    __syncthreads();
#pragma unroll
    for (int j = 0; j < NSLOT; ++j)
        sts64(blk1 + 8u * j, y2[j]);
    __syncthreads();
#pragma unroll
    for (int j = 0; j < NSLOT; ++j) {
        y2[j] = lds64(til1 + 136u * j);
        rl[j] = lds64(til0 + 136u * j);
    }

    // ---- Phase B: d=32,64,128,256 ----
    { COEFFS(7) levelB<1, 10, true >(rl, y2, til0, til1, tge1, tge2, a0, a1, a2, a3, b0, b1, b2, b3); }
    { COEFFS(6) levelB<2,  4, true >(rl, y2, til1, til0, tge1, tge2, a0, a1, a2, a3, b0, b1, b2, b3); }
    { COEFFS(5) levelB<4,  0, true >(rl, y2, til0, til1, tge1, tge2, a0, a1, a2, a3, b0, b1, b2, b3); }
    { COEFFS(4) levelB<8,  0, true >(rl, y2, til1, til0, tge1, tge2, a0, a1, a2, a3, b0, b1, b2, b3); }

    // ---- T2: tile16 -> cyclic-256 ----
    __syncthreads();
#pragma unroll
    for (int j = 0; j < NSLOT; ++j)
        sts64(til1 + 136u * j, y2[j]);
    __syncthreads();
#pragma unroll
    for (int k = 0; k < NSLOT; ++k) {
        y2[k] = lds64(cyc1 + 2176u * k);
        rl[k] = lds64(cyc0 + 2176u * k);
    }

    // ---- Phase C: d=512,1024,2048 — pure register ----
    { COEFFS(3) levelC<1>(rl, y2, a0, a1, a2, a3, b0, b1, b2, b3); }
    { COEFFS(2) levelC<2>(rl, y2, a0, a1, a2, a3, b0, b1, b2, b3); }
    { COEFFS(1) levelC<4>(rl, y2, a0, a1, a2, a3, b0, b1, b2, b3); }
#undef COEFFS

    // ---- final: y += w0*res_lo; exact GELU; coalesced STG.64 (cyclic) ----
    {
        const float w0v = __ldg(wc + 0);
        const u64 w0p = pk2(w0v, w0v);
        float2* o2 = (float2*)(out + (size_t)row * L_LEN);
#pragma unroll
        for (int k = 0; k < NSLOT; ++k) {
            u64 yf = fma2(w0p, rl[k], y2[k]);
            float lo, hi; upk2(yf, lo, hi);
            lo = 0.5f * lo * (1.0f + erff(lo * 0.70710678118654752f));
            hi = 0.5f * hi * (1.0f + erff(hi * 0.70710678118654752f));
            o2[tid + 256 * k] = make_float2(lo, hi);
        }
    }
}

extern "C" void kernel_launch(void* const* d_in, const int* in_sizes, int n_in,
                              void* d_out, int out_size)
{
    (void)in_sizes; (void)n_in; (void)out_size;
    const float* x  = (const float*)d_in[0];
    const float* h0 = (const float*)d_in[1];
    const float* h1 = (const float*)d_in[2];
    const float* w  = (const float*)d_in[3];
    float* out = (float*)d_out;

    const int smem_bytes = 2 * BUFB + 128;   // 69,760 B
    cudaFuncSetAttribute(mr_kernel, cudaFuncAttributeMaxDynamicSharedMemorySize, smem_bytes);
    mr_kernel<<<B_N * C_CH, NTH, smem_bytes>>>(x, h0, h1, w, out);
}